// round 1
// baseline (speedup 1.0000x reference)
#include <cuda_runtime.h>

#define NCLS   2048
#define NROWS  32768
#define BLOCK  256
#define GRID   (NROWS / BLOCK)   // 128

__device__ double g_partials[GRID];

__global__ __launch_bounds__(BLOCK) void mpl_main(const float* __restrict__ x,
                                                  const int* __restrict__ tgt) {
    __shared__ int   s_zero_rows[BLOCK];
    __shared__ int   s_zero_count;
    __shared__ float s_warp[BLOCK / 32];

    const int tid  = threadIdx.x;
    const int lane = tid & 31;
    const int wid  = tid >> 5;

    if (tid == 0) s_zero_count = 0;
    __syncthreads();

    const int row = blockIdx.x * BLOCK + tid;
    const int t   = tgt[row];

    float local = 0.0f;
    if (t != 0) {
        // positive set = {1..C-1}; reference loss collapses to 2-class logistic:
        // loss = log(exp(x0) + exp(xt)) - xt
        const float x0 = __ldg(&x[(size_t)row * NCLS]);
        const float xt = __ldg(&x[(size_t)row * NCLS + t]);
        local = __logf(__expf(x0) + __expf(xt)) - xt;
    } else {
        const int slot = atomicAdd(&s_zero_count, 1);
        s_zero_rows[slot] = row;
    }
    __syncthreads();

    // Rare path: full-row logsumexp for rows whose target == 0.
    // neg_sum + exp(x_t) with t=0 equals the FULL row sum of exps.
    double zacc = 0.0;            // only meaningful on tid 0
    const int nz = s_zero_count;
    for (int k = 0; k < nz; k++) {
        const int zrow = s_zero_rows[k];
        const float4* rp = reinterpret_cast<const float4*>(x + (size_t)zrow * NCLS);
        float s = 0.0f;
        #pragma unroll
        for (int j = tid; j < NCLS / 4; j += BLOCK) {
            const float4 v = __ldg(&rp[j]);
            s += __expf(v.x) + __expf(v.y) + __expf(v.z) + __expf(v.w);
        }
        // block reduce s
        #pragma unroll
        for (int off = 16; off > 0; off >>= 1)
            s += __shfl_down_sync(0xFFFFFFFFu, s, off);
        if (lane == 0) s_warp[wid] = s;
        __syncthreads();
        if (wid == 0) {
            float ws = (lane < BLOCK / 32) ? s_warp[lane] : 0.0f;
            #pragma unroll
            for (int off = 4; off > 0; off >>= 1)
                ws += __shfl_down_sync(0xFFFFFFFFu, ws, off);
            if (lane == 0) {
                const float x0 = __ldg(&x[(size_t)zrow * NCLS]);
                zacc += (double)(__logf(ws) - x0);
            }
        }
        __syncthreads();
    }

    // Block reduce of the cheap-path losses
    float r = local;
    #pragma unroll
    for (int off = 16; off > 0; off >>= 1)
        r += __shfl_down_sync(0xFFFFFFFFu, r, off);
    if (lane == 0) s_warp[wid] = r;
    __syncthreads();
    if (wid == 0) {
        float ws = (lane < BLOCK / 32) ? s_warp[lane] : 0.0f;
        #pragma unroll
        for (int off = 4; off > 0; off >>= 1)
            ws += __shfl_down_sync(0xFFFFFFFFu, ws, off);
        if (lane == 0)
            g_partials[blockIdx.x] = (double)ws + zacc;
    }
}

__global__ __launch_bounds__(128) void mpl_finalize(float* __restrict__ out) {
    __shared__ double s_warp[4];
    const int tid  = threadIdx.x;
    const int lane = tid & 31;
    const int wid  = tid >> 5;

    double v = g_partials[tid];   // 128 threads, 128 partials
    #pragma unroll
    for (int off = 16; off > 0; off >>= 1)
        v += __shfl_down_sync(0xFFFFFFFFu, v, off);
    if (lane == 0) s_warp[wid] = v;
    __syncthreads();
    if (tid == 0) {
        double s = s_warp[0] + s_warp[1] + s_warp[2] + s_warp[3];
        out[0] = (float)(s / (double)NROWS);
    }
}

extern "C" void kernel_launch(void* const* d_in, const int* in_sizes, int n_in,
                              void* d_out, int out_size) {
    const float* x   = (const float*)d_in[0];
    const int*   tgt = (const int*)d_in[1];
    float*       out = (float*)d_out;

    mpl_main<<<GRID, BLOCK>>>(x, tgt);
    mpl_finalize<<<1, 128>>>(out);
}